// round 14
// baseline (speedup 1.0000x reference)
#include <cuda_runtime.h>
#include <cstdint>

#define G_TOT   1024
#define WSZ     16
#define HDIM    16
#define B_ROWS  8192
#define GTILE   16                    // groups per CTA column tile
#define HSPLIT  8                     // threads per group along H (2 h each)
#define BLOCK   (GTILE * HSPLIT)      // 128 threads
#define CHUNK_ROWS 8
#define STAGES  3
#define ROWSTRIDE 16384               // floats per x/out row (G*16)
#define SLICE   (GTILE * WSZ)         // 256 floats per row-slice (1KB)
#define STAGE_FLOATS (CHUNK_ROWS * SLICE)               // 2048 floats
#define STAGE_BYTES  (STAGE_FLOATS * 4)                 // 8 KB
#define CHUNKS_PER_GT (B_ROWS / CHUNK_ROWS)             // 1024
#define NCHUNKS_TOT   (CHUNKS_PER_GT * (G_TOT / GTILE)) // 65536

__device__ __forceinline__ unsigned long long pack2(float lo, float hi) {
    unsigned long long r;
    asm("mov.b64 %0, {%1, %2};" : "=l"(r) : "f"(lo), "f"(hi));
    return r;
}
__device__ __forceinline__ void unpack2(unsigned long long v, float& lo, float& hi) {
    asm("mov.b64 {%0, %1}, %2;" : "=f"(lo), "=f"(hi) : "l"(v));
}
// d = a * b + d  (packed f32x2 — ptxas never auto-emits FFMA2)
__device__ __forceinline__ void ffma2(unsigned long long& d,
                                      unsigned long long a, unsigned long long b) {
    asm("fma.rn.f32x2 %0, %1, %2, %0;" : "+l"(d) : "l"(a), "l"(b));
}
__device__ __forceinline__ uint32_t smem_u32(const void* p) {
    return (uint32_t)__cvta_generic_to_shared(p);
}
__device__ __forceinline__ void cp_async16(uint32_t dst, const void* src) {
    asm volatile("cp.async.cg.shared.global [%0], [%1], 16;" :: "r"(dst), "l"(src));
}

__global__ void __launch_bounds__(BLOCK, 8)
bd_kernel(const float* __restrict__ x, const float* __restrict__ W,
          float* __restrict__ out)
{
    __shared__ float xs[STAGES * STAGE_FLOATS];   // 24 KB

    const int tid = threadIdx.x;
    const int hq  = tid & (HSPLIT - 1);
    const int gl  = tid >> 3;             // local group (0..15)

    // flattened persistent split: single wave, balanced ±1 chunk, no tail
    const int c0 = (int)((long long)blockIdx.x       * NCHUNKS_TOT / gridDim.x);
    const int c1 = (int)((long long)(blockIdx.x + 1) * NCHUNKS_TOT / gridDim.x);
    const int n  = c1 - c0;

    // ---- loader: 64 16B units per row; thread t -> unit (t&63) of rows (t>>6)+{0,2,4,6}
    const int lrl  = tid >> 6;                         // base row within chunk (0/1)
    const uint32_t dst0 = smem_u32(xs) + lrl * 1024 + (tid & 63) * 16;

    int lgt  = c0 >> 10;                               // c / CHUNKS_PER_GT
    int lrow = (c0 & (CHUNKS_PER_GT - 1)) * CHUNK_ROWS;
    const float* lsrcT = x + (size_t)(lrow + lrl) * ROWSTRIDE
                           + lgt * SLICE + (tid & 63) * 4;
    int lslot = 0;

    auto issue_load = [&]() {
        const uint32_t d = dst0 + lslot * STAGE_BYTES;
        cp_async16(d,        lsrcT);
        cp_async16(d + 2048, lsrcT + 2 * ROWSTRIDE);
        cp_async16(d + 4096, lsrcT + 4 * ROWSTRIDE);
        cp_async16(d + 6144, lsrcT + 6 * ROWSTRIDE);
        asm volatile("cp.async.commit_group;");
        lrow  += CHUNK_ROWS;
        lsrcT += CHUNK_ROWS * ROWSTRIDE;
        if (lrow == B_ROWS) {                          // <=1 crossing per CTA
            lrow = 0; ++lgt;
            lsrcT = x + (size_t)lrl * ROWSTRIDE + lgt * SLICE + (tid & 63) * 4;
        }
        if (++lslot == STAGES) lslot = 0;
    };

    // prologue: fill pipeline (commit empty groups to keep counts aligned)
    for (int i = 0; i < STAGES - 1; ++i) {
        if (i < n) issue_load();
        else       asm volatile("cp.async.commit_group;");
    }

    // ---- compute state (incremental) ----
    int cgt  = c0 >> 10;
    int crow = (c0 & (CHUNKS_PER_GT - 1)) * CHUNK_ROWS;
    float* optrT = out + (size_t)crow * ROWSTRIDE
                       + (cgt * GTILE + gl) * HDIM + hq * 2;
    int cslot = 0;
    int need_w = 1;
    unsigned long long w2[WSZ / 2][2];

    for (int k = 0; k < n; ++k) {
        if (need_w) {                                  // rare: <=1 per CTA + start
            need_w = 0;
            const float* wg = W + (size_t)(cgt * GTILE + gl) * (WSZ * HDIM) + hq * 2;
#pragma unroll
            for (int k2 = 0; k2 < WSZ / 2; ++k2) {
                float2 a = *(const float2*)(wg + (2 * k2)     * HDIM);
                float2 b = *(const float2*)(wg + (2 * k2 + 1) * HDIM);
                w2[k2][0] = pack2(a.x, b.x);
                w2[k2][1] = pack2(a.y, b.y);
            }
        }

        asm volatile("cp.async.wait_group %0;" :: "n"(STAGES - 2));
        __syncthreads();   // 4-warp barrier: chunk k resident; oldest slot free

        if (k + STAGES - 1 < n) issue_load();
        else asm volatile("cp.async.commit_group;");

        const float* xb = xs + cslot * STAGE_FLOATS + gl * WSZ;
#pragma unroll
        for (int rl = 0; rl < CHUNK_ROWS; ++rl) {
            const ulonglong2* xq = (const ulonglong2*)(xb + rl * SLICE);
            unsigned long long a0 = 0ull, a1 = 0ull;
            {   // k 0..7 (register-lean halves, as in R13)
                ulonglong2 qa = xq[0], qb = xq[1];
                ffma2(a0, qa.x, w2[0][0]); ffma2(a1, qa.x, w2[0][1]);
                ffma2(a0, qa.y, w2[1][0]); ffma2(a1, qa.y, w2[1][1]);
                ffma2(a0, qb.x, w2[2][0]); ffma2(a1, qb.x, w2[2][1]);
                ffma2(a0, qb.y, w2[3][0]); ffma2(a1, qb.y, w2[3][1]);
            }
            {   // k 8..15
                ulonglong2 qa = xq[2], qb = xq[3];
                ffma2(a0, qa.x, w2[4][0]); ffma2(a1, qa.x, w2[4][1]);
                ffma2(a0, qa.y, w2[5][0]); ffma2(a1, qa.y, w2[5][1]);
                ffma2(a0, qb.x, w2[6][0]); ffma2(a1, qb.x, w2[6][1]);
                ffma2(a0, qb.y, w2[7][0]); ffma2(a1, qb.y, w2[7][1]);
            }
            float l0, h0, l1, h1;
            unpack2(a0, l0, h0);
            unpack2(a1, l1, h1);
            float2 o;
            o.x = fmaxf(l0 + h0, 0.0f);     // k-pair horizontal reduce + ReLU
            o.y = fmaxf(l1 + h1, 0.0f);
            *(float2*)(optrT + (size_t)rl * ROWSTRIDE) = o;  // immediate offsets
        }

        crow  += CHUNK_ROWS;
        optrT += CHUNK_ROWS * ROWSTRIDE;
        if (crow == B_ROWS) {
            crow = 0; ++cgt; need_w = 1;
            optrT = out + (size_t)(cgt * GTILE + gl) * HDIM + hq * 2;
        }
        if (++cslot == STAGES) cslot = 0;
    }
}

extern "C" void kernel_launch(void* const* d_in, const int* in_sizes, int n_in,
                              void* d_out, int out_size) {
    const float* x = (const float*)d_in[0];   // (8192, 16384) f32
    const float* W = (const float*)d_in[1];   // (1024, 16, 16) f32
    float* out = (float*)d_out;               // (8192, 16384) f32

    int sms = 148;
    cudaDeviceGetAttribute(&sms, cudaDevAttrMultiProcessorCount, 0);
    dim3 grid(sms * 8);                        // one wave: 8 CTAs/SM x 128 threads
    bd_kernel<<<grid, BLOCK>>>(x, W, out);
}

// round 15
// speedup vs baseline: 1.0263x; 1.0263x over previous
#include <cuda_runtime.h>
#include <cstdint>

#define G_TOT   1024
#define WSZ     16
#define HDIM    16
#define B_ROWS  8192
#define GTILE   32                    // groups per CTA column tile
#define HSPLIT  8                     // threads per group along H (2 h each)
#define BLOCK   (GTILE * HSPLIT)      // 256 threads
#define CHUNK_ROWS 8
#define STAGES  3
#define ROWSTRIDE 16384               // floats per x/out row (G*16)
#define SLICE   (GTILE * WSZ)         // 512 floats per row-slice
#define STAGE_BYTES (CHUNK_ROWS * SLICE * 4)            // 16 KB
#define CHUNKS_PER_GT (B_ROWS / CHUNK_ROWS)             // 1024
#define NCHUNKS_TOT   (CHUNKS_PER_GT * (G_TOT / GTILE)) // 32768

__device__ __forceinline__ unsigned long long pack2(float lo, float hi) {
    unsigned long long r;
    asm("mov.b64 %0, {%1, %2};" : "=l"(r) : "f"(lo), "f"(hi));
    return r;
}
__device__ __forceinline__ void unpack2(unsigned long long v, float& lo, float& hi) {
    asm("mov.b64 {%0, %1}, %2;" : "=f"(lo), "=f"(hi) : "l"(v));
}
// d = a * b + d  (packed f32x2 — ptxas never auto-emits FFMA2)
__device__ __forceinline__ void ffma2(unsigned long long& d,
                                      unsigned long long a, unsigned long long b) {
    asm("fma.rn.f32x2 %0, %1, %2, %0;" : "+l"(d) : "l"(a), "l"(b));
}
__device__ __forceinline__ uint32_t smem_u32(const void* p) {
    return (uint32_t)__cvta_generic_to_shared(p);
}
__device__ __forceinline__ void cp_async16(uint32_t dst, const void* src) {
    asm volatile("cp.async.cg.shared.global [%0], [%1], 16;" :: "r"(dst), "l"(src));
}

__global__ void __launch_bounds__(BLOCK, 4)
bd_kernel(const float* __restrict__ x, const float* __restrict__ W,
          float* __restrict__ out)
{
    __shared__ float xs[STAGES][CHUNK_ROWS * SLICE];   // 48 KB

    const int tid = threadIdx.x;
    const int hq  = tid & (HSPLIT - 1);
    const int gl  = tid >> 3;

    // flattened persistent split: single wave, balanced ±1 chunk, no tail
    const int c0 = (int)((long long)blockIdx.x       * NCHUNKS_TOT / gridDim.x);
    const int c1 = (int)((long long)(blockIdx.x + 1) * NCHUNKS_TOT / gridDim.x);
    const int n  = c1 - c0;

    // ---- loader: per-thread constants -> 4 immediate-offset cp.async per chunk
    const int lrl  = tid >> 7;                         // base row within chunk (0/1)
    const uint32_t dst0 = smem_u32(&xs[0][0]) + lrl * 2048 + (tid & 127) * 16;

    int lgt  = c0 >> 10;
    int lrow = (c0 & (CHUNKS_PER_GT - 1)) * CHUNK_ROWS;
    const float* lsrcT = x + (size_t)(lrow + lrl) * ROWSTRIDE
                           + lgt * SLICE + (tid & 127) * 4;
    int lslot = 0;

    auto issue_load = [&]() {
        const uint32_t d = dst0 + lslot * STAGE_BYTES;
        cp_async16(d,         lsrcT);
        cp_async16(d + 4096,  lsrcT + 2 * ROWSTRIDE);
        cp_async16(d + 8192,  lsrcT + 4 * ROWSTRIDE);
        cp_async16(d + 12288, lsrcT + 6 * ROWSTRIDE);
        asm volatile("cp.async.commit_group;");
        lrow  += CHUNK_ROWS;
        lsrcT += CHUNK_ROWS * ROWSTRIDE;
        if (lrow == B_ROWS) {                          // <=1 crossing per CTA
            lrow = 0; ++lgt;
            lsrcT = x + (size_t)lrl * ROWSTRIDE + lgt * SLICE + (tid & 127) * 4;
        }
        if (++lslot == STAGES) lslot = 0;
    };

    // prologue: fill pipeline (commit empty groups to keep counts aligned)
    for (int i = 0; i < STAGES - 1; ++i) {
        if (i < n) issue_load();
        else       asm volatile("cp.async.commit_group;");
    }

    // ---- compute state (incremental) ----
    int cgt  = c0 >> 10;
    int crow = (c0 & (CHUNKS_PER_GT - 1)) * CHUNK_ROWS;
    float* optrT = out + (size_t)crow * ROWSTRIDE
                       + (cgt * GTILE + gl) * HDIM + hq * 2;
    int cslot = 0;
    int need_w = 1;
    unsigned long long w2[WSZ / 2][2];

    for (int k = 0; k < n; ++k) {
        if (need_w) {                                  // rare: <=1 per CTA + start
            need_w = 0;
            const float* wg = W + (size_t)(cgt * GTILE + gl) * (WSZ * HDIM) + hq * 2;
#pragma unroll
            for (int k2 = 0; k2 < WSZ / 2; ++k2) {
                float2 a = *(const float2*)(wg + (2 * k2)     * HDIM);
                float2 b = *(const float2*)(wg + (2 * k2 + 1) * HDIM);
                w2[k2][0] = pack2(a.x, b.x);
                w2[k2][1] = pack2(a.y, b.y);
            }
        }

        asm volatile("cp.async.wait_group %0;" :: "n"(STAGES - 2));
        __syncthreads();   // chunk k resident; slot (k+2)%3 reads finished at k-1

        if (k + STAGES - 1 < n) issue_load();
        else asm volatile("cp.async.commit_group;");

        const float* xb = &xs[0][0] + cslot * (CHUNK_ROWS * SLICE) + gl * WSZ;
#pragma unroll
        for (int rl = 0; rl < CHUNK_ROWS; ++rl) {
            const ulonglong2* xq = (const ulonglong2*)(xb + rl * SLICE);
            unsigned long long a0 = 0ull, a1 = 0ull;
            {   // first half: k 0..7 (register-lean halves, as in R13)
                ulonglong2 qa = xq[0], qb = xq[1];
                ffma2(a0, qa.x, w2[0][0]); ffma2(a1, qa.x, w2[0][1]);
                ffma2(a0, qa.y, w2[1][0]); ffma2(a1, qa.y, w2[1][1]);
                ffma2(a0, qb.x, w2[2][0]); ffma2(a1, qb.x, w2[2][1]);
                ffma2(a0, qb.y, w2[3][0]); ffma2(a1, qb.y, w2[3][1]);
            }
            {   // second half: k 8..15
                ulonglong2 qa = xq[2], qb = xq[3];
                ffma2(a0, qa.x, w2[4][0]); ffma2(a1, qa.x, w2[4][1]);
                ffma2(a0, qa.y, w2[5][0]); ffma2(a1, qa.y, w2[5][1]);
                ffma2(a0, qb.x, w2[6][0]); ffma2(a1, qb.x, w2[6][1]);
                ffma2(a0, qb.y, w2[7][0]); ffma2(a1, qb.y, w2[7][1]);
            }
            float l0, h0, l1, h1;
            unpack2(a0, l0, h0);
            unpack2(a1, l1, h1);
            float2 o;
            o.x = fmaxf(l0 + h0, 0.0f);     // k-pair horizontal reduce + ReLU
            o.y = fmaxf(l1 + h1, 0.0f);
            __stcs((float2*)(optrT + (size_t)rl * ROWSTRIDE), o);  // evict-first
        }

        crow  += CHUNK_ROWS;
        optrT += CHUNK_ROWS * ROWSTRIDE;
        if (crow == B_ROWS) {
            crow = 0; ++cgt; need_w = 1;
            optrT = out + (size_t)(cgt * GTILE + gl) * HDIM + hq * 2;
        }
        if (++cslot == STAGES) cslot = 0;
    }
}

extern "C" void kernel_launch(void* const* d_in, const int* in_sizes, int n_in,
                              void* d_out, int out_size) {
    const float* x = (const float*)d_in[0];   // (8192, 16384) f32
    const float* W = (const float*)d_in[1];   // (1024, 16, 16) f32
    float* out = (float*)d_out;               // (8192, 16384) f32

    int sms = 148;
    cudaDeviceGetAttribute(&sms, cudaDevAttrMultiProcessorCount, 0);
    dim3 grid(sms * 4);                        // one wave at occ=4 (32 warps/SM)
    bd_kernel<<<grid, BLOCK>>>(x, W, out);
}

// round 16
// speedup vs baseline: 1.0377x; 1.0112x over previous
#include <cuda_runtime.h>
#include <cstdint>

#define G_TOT   1024
#define WSZ     16
#define HDIM    16
#define B_ROWS  8192
#define GTILE   32                    // groups per CTA column tile
#define HSPLIT  8                     // threads per group along H (2 h each)
#define BLOCK   (GTILE * HSPLIT)      // 256 threads
#define CHUNK_ROWS 8
#define STAGES  3
#define ROWSTRIDE 16384               // floats per x/out row (G*16)
#define SLICE   (GTILE * WSZ)         // 512 floats per row-slice
#define STAGE_BYTES (CHUNK_ROWS * SLICE * 4)            // 16 KB
#define CHUNKS_PER_GT (B_ROWS / CHUNK_ROWS)             // 1024
#define NCHUNKS_TOT   (CHUNKS_PER_GT * (G_TOT / GTILE)) // 32768

__device__ __forceinline__ unsigned long long pack2(float lo, float hi) {
    unsigned long long r;
    asm("mov.b64 %0, {%1, %2};" : "=l"(r) : "f"(lo), "f"(hi));
    return r;
}
__device__ __forceinline__ void unpack2(unsigned long long v, float& lo, float& hi) {
    asm("mov.b64 {%0, %1}, %2;" : "=f"(lo), "=f"(hi) : "l"(v));
}
// d = a * b + d  (packed f32x2 — ptxas never auto-emits FFMA2)
__device__ __forceinline__ void ffma2(unsigned long long& d,
                                      unsigned long long a, unsigned long long b) {
    asm("fma.rn.f32x2 %0, %1, %2, %0;" : "+l"(d) : "l"(a), "l"(b));
}
__device__ __forceinline__ uint32_t smem_u32(const void* p) {
    return (uint32_t)__cvta_generic_to_shared(p);
}
__device__ __forceinline__ void cp_async16(uint32_t dst, const void* src) {
    asm volatile("cp.async.cg.shared.global [%0], [%1], 16;" :: "r"(dst), "l"(src));
}

__global__ void __launch_bounds__(BLOCK, 4)
bd_kernel(const float* __restrict__ x, const float* __restrict__ W,
          float* __restrict__ out)
{
    __shared__ float xs[STAGES][CHUNK_ROWS * SLICE];   // 48 KB

    const int tid = threadIdx.x;
    const int hq  = tid & (HSPLIT - 1);
    const int gl  = tid >> 3;

    // flattened persistent split: single wave, balanced ±1 chunk, no tail
    const int c0 = (int)((long long)blockIdx.x       * NCHUNKS_TOT / gridDim.x);
    const int c1 = (int)((long long)(blockIdx.x + 1) * NCHUNKS_TOT / gridDim.x);
    const int n  = c1 - c0;

    // ---- loader: per-thread constants -> 4 immediate-offset cp.async per chunk
    const int lrl  = tid >> 7;                         // base row within chunk (0/1)
    const uint32_t dst0 = smem_u32(&xs[0][0]) + lrl * 2048 + (tid & 127) * 16;

    int lgt  = c0 >> 10;
    int lrow = (c0 & (CHUNKS_PER_GT - 1)) * CHUNK_ROWS;
    const float* lsrcT = x + (size_t)(lrow + lrl) * ROWSTRIDE
                           + lgt * SLICE + (tid & 127) * 4;
    int lslot = 0;

    auto issue_load = [&]() {
        const uint32_t d = dst0 + lslot * STAGE_BYTES;
        cp_async16(d,         lsrcT);
        cp_async16(d + 4096,  lsrcT + 2 * ROWSTRIDE);
        cp_async16(d + 8192,  lsrcT + 4 * ROWSTRIDE);
        cp_async16(d + 12288, lsrcT + 6 * ROWSTRIDE);
        asm volatile("cp.async.commit_group;");
        lrow  += CHUNK_ROWS;
        lsrcT += CHUNK_ROWS * ROWSTRIDE;
        if (lrow == B_ROWS) {                          // <=1 crossing per CTA
            lrow = 0; ++lgt;
            lsrcT = x + (size_t)lrl * ROWSTRIDE + lgt * SLICE + (tid & 127) * 4;
        }
        if (++lslot == STAGES) lslot = 0;
    };

    // prologue: fill pipeline (commit empty groups to keep counts aligned)
    for (int i = 0; i < STAGES - 1; ++i) {
        if (i < n) issue_load();
        else       asm volatile("cp.async.commit_group;");
    }

    // ---- compute state (incremental) ----
    int cgt  = c0 >> 10;
    int crow = (c0 & (CHUNKS_PER_GT - 1)) * CHUNK_ROWS;
    float* optrT = out + (size_t)crow * ROWSTRIDE
                       + (cgt * GTILE + gl) * HDIM + hq * 2;
    int cslot = 0;
    int need_w = 1;
    unsigned long long w2[WSZ / 2][2];

    for (int k = 0; k < n; ++k) {
        if (need_w) {                                  // rare: <=1 per CTA + start
            need_w = 0;
            const float* wg = W + (size_t)(cgt * GTILE + gl) * (WSZ * HDIM) + hq * 2;
#pragma unroll
            for (int k2 = 0; k2 < WSZ / 2; ++k2) {
                float2 a = *(const float2*)(wg + (2 * k2)     * HDIM);
                float2 b = *(const float2*)(wg + (2 * k2 + 1) * HDIM);
                w2[k2][0] = pack2(a.x, b.x);
                w2[k2][1] = pack2(a.y, b.y);
            }
        }

        asm volatile("cp.async.wait_group %0;" :: "n"(STAGES - 2));
        __syncthreads();   // chunk k resident; slot (k+2)%3 reads finished at k-1

        if (k + STAGES - 1 < n) issue_load();
        else asm volatile("cp.async.commit_group;");

        const float* xb = &xs[0][0] + cslot * (CHUNK_ROWS * SLICE) + gl * WSZ;
#pragma unroll
        for (int rl = 0; rl < CHUNK_ROWS; ++rl) {
            const ulonglong2* xq = (const ulonglong2*)(xb + rl * SLICE);
            unsigned long long a0 = 0ull, a1 = 0ull;
            {   // first half: k 0..7 (two LDS.128, register-lean)
                ulonglong2 qa = xq[0], qb = xq[1];
                ffma2(a0, qa.x, w2[0][0]); ffma2(a1, qa.x, w2[0][1]);
                ffma2(a0, qa.y, w2[1][0]); ffma2(a1, qa.y, w2[1][1]);
                ffma2(a0, qb.x, w2[2][0]); ffma2(a1, qb.x, w2[2][1]);
                ffma2(a0, qb.y, w2[3][0]); ffma2(a1, qb.y, w2[3][1]);
            }
            {   // second half: k 8..15
                ulonglong2 qa = xq[2], qb = xq[3];
                ffma2(a0, qa.x, w2[4][0]); ffma2(a1, qa.x, w2[4][1]);
                ffma2(a0, qa.y, w2[5][0]); ffma2(a1, qa.y, w2[5][1]);
                ffma2(a0, qb.x, w2[6][0]); ffma2(a1, qb.x, w2[6][1]);
                ffma2(a0, qb.y, w2[7][0]); ffma2(a1, qb.y, w2[7][1]);
            }
            float l0, h0, l1, h1;
            unpack2(a0, l0, h0);
            unpack2(a1, l1, h1);
            float2 o;
            o.x = fmaxf(l0 + h0, 0.0f);     // k-pair horizontal reduce + ReLU
            o.y = fmaxf(l1 + h1, 0.0f);
            *(float2*)(optrT + (size_t)rl * ROWSTRIDE) = o;  // immediate offsets
        }

        crow  += CHUNK_ROWS;
        optrT += CHUNK_ROWS * ROWSTRIDE;
        if (crow == B_ROWS) {
            crow = 0; ++cgt; need_w = 1;
            optrT = out + (size_t)(cgt * GTILE + gl) * HDIM + hq * 2;
        }
        if (++cslot == STAGES) cslot = 0;
    }
}

extern "C" void kernel_launch(void* const* d_in, const int* in_sizes, int n_in,
                              void* d_out, int out_size) {
    const float* x = (const float*)d_in[0];   // (8192, 16384) f32
    const float* W = (const float*)d_in[1];   // (1024, 16, 16) f32
    float* out = (float*)d_out;               // (8192, 16384) f32

    int sms = 148;
    cudaDeviceGetAttribute(&sms, cudaDevAttrMultiProcessorCount, 0);
    dim3 grid(sms * 4);                        // one wave at occ=4 (32 warps/SM)
    bd_kernel<<<grid, BLOCK>>>(x, W, out);
}